// round 5
// baseline (speedup 1.0000x reference)
#include <cuda_runtime.h>
#include <cstdint>

// MXFP4-style group quantizer, group_size=32, ebits=2, mbits=1.
// max_val = 2^(2^2-1) * (2 - 2^-1) = 12 ;  clamp_max = 8
//
// __output__ is float32: each element holds the numeric value (0..255) of the
// corresponding uint8 from the reference's concatenated [packed_bytes, scales].
//
// Thread t loads float4 at element 4t = elements 4l..4l+3 of group g = t>>3
// (l = t&7). Those yield packed bytes 2l, 2l+1 of group g = output float
// indices 2t, 2t+1 -> one float2 store. Input and output both perfectly
// coalesced (warp: 512 B load, 256 B store). Absmax reduces over the 8-lane
// subgroup via shfl.xor 1,2,4; lane l==0 writes the group's scale float.
//
// Quantization path uses __fdiv_rn/__fmul_rn so it is bit-exact vs the JAX
// float32 reference (x / gmax * 12, RNE at each step) even under fast-math.

__global__ void __launch_bounds__(256) mx_quant_kernel(
    const float4* __restrict__ x4,
    float2* __restrict__ out_packed,       // N/2 floats viewed as float2[N/4]
    float*  __restrict__ out_scale)        // N/32 floats
{
    const long long t = (long long)blockIdx.x * blockDim.x + threadIdx.x;

    float4 v = x4[t];

    // abs-max over this thread's 4 values
    float m = fmaxf(fmaxf(fabsf(v.x), fabsf(v.y)),
                    fmaxf(fabsf(v.z), fabsf(v.w)));
    // reduce across the 8-lane subgroup (one group of 32 elements)
    m = fmaxf(m, __shfl_xor_sync(0xFFFFFFFFu, m, 1));
    m = fmaxf(m, __shfl_xor_sync(0xFFFFFFFFu, m, 2));
    m = fmaxf(m, __shfl_xor_sync(0xFFFFFFFFu, m, 4));

    const float gmax = fmaxf(m, 1e-12f);

    // q = rint(clip(x/gmax*12, -8, 8)) ; u = min(q+8, 15)   (u in 0..15)
    // __fdiv_rn + __fmul_rn: same two RNE roundings as the reference.
    #define QUANT(val, u)                                              \
    {                                                                  \
        float s = __fmul_rn(__fdiv_rn((val), gmax), 12.0f);            \
        s = fminf(fmaxf(s, -8.0f), 8.0f);                              \
        int q = (int)rintf(s);                                         \
        u = min(q + 8, 15);                                            \
    }
    int u0, u1, u2, u3;
    QUANT(v.x, u0); QUANT(v.y, u1); QUANT(v.z, u2); QUANT(v.w, u3);
    #undef QUANT

    // packed byte values (as numbers): even elem -> low nibble, odd -> high
    float2 pk;
    pk.x = (float)(u0 | (u1 << 4));
    pk.y = (float)(u2 | (u3 << 4));
    out_packed[t] = pk;

    // one scale value per group, written by subgroup lane 0
    if ((threadIdx.x & 7u) == 0u) {
        float ls = log2f(gmax);
        ls = fminf(fmaxf(ls, -127.0f), 127.0f);
        out_scale[t >> 3] = rintf(ls + 127.0f);
    }
}

extern "C" void kernel_launch(void* const* d_in, const int* in_sizes, int n_in,
                              void* d_out, int out_size)
{
    const float* x = (const float*)d_in[0];
    const long long N = (long long)in_sizes[0];   // 67108864

    float* out = (float*)d_out;                   // [N/2 packed | N/32 scales]
    const long long threads_total = N / 4;        // one float4 per thread
    const int  block = 256;
    const long long grid = threads_total / block; // N divisible by 1024

    mx_quant_kernel<<<(unsigned int)grid, block>>>(
        (const float4*)x,
        (float2*)out,
        out + (N / 2));
}

// round 14
// speedup vs baseline: 1.3566x; 1.3566x over previous
#include <cuda_runtime.h>
#include <cstdint>

// MXFP4-style group quantizer, group_size=32, ebits=2, mbits=1.
// max_val = 12, clamp_max = 8. Output is float32 holding uint8 values
// [packed_bytes (N/2) | scale_bytes (N/32)].
//
// Thread t owns 8 consecutive elements 8t..8t+7 (two float4 loads) = quarter
// of group g = t>>2. Absmax over the 4-lane subgroup via shfl.xor 1,2.
// Quantize + pack entirely in FP (values are small integers, exact in f32):
//   q' = min(rint(clamp(x*(12/gmax), -8, 8)), 7)        in [-8,7]
//   byte = (q_even+8) | (q_odd+8)<<4 = q_even + 16*q_odd + 136
// Packed bytes 4t..4t+3 -> one float4 store at index t: in/out coalesced.

__global__ void __launch_bounds__(256) mx_quant_kernel(
    const float4* __restrict__ x4,
    float4* __restrict__ out_packed,   // N/2 floats viewed as float4[N/8]
    float*  __restrict__ out_scale)    // N/32 floats
{
    const unsigned t = blockIdx.x * blockDim.x + threadIdx.x;

    const float4 a = x4[2u * t];
    const float4 b = x4[2u * t + 1u];

    // abs-max over this thread's 8 values
    float m = fmaxf(
        fmaxf(fmaxf(fabsf(a.x), fabsf(a.y)), fmaxf(fabsf(a.z), fabsf(a.w))),
        fmaxf(fmaxf(fabsf(b.x), fabsf(b.y)), fmaxf(fabsf(b.z), fabsf(b.w))));
    // reduce across the 4-lane subgroup (one group of 32 elements)
    m = fmaxf(m, __shfl_xor_sync(0xFFFFFFFFu, m, 1));
    m = fmaxf(m, __shfl_xor_sync(0xFFFFFFFFu, m, 2));

    const float gmax = fmaxf(m, 1e-12f);
    const float s12  = __fdividef(12.0f, gmax);   // one fast divide / 8 elems

    #define Q(val) fminf(rintf(fminf(fmaxf((val) * s12, -8.0f), 8.0f)), 7.0f)
    const float q0 = Q(a.x), q1 = Q(a.y), q2 = Q(a.z), q3 = Q(a.w);
    const float q4 = Q(b.x), q5 = Q(b.y), q6 = Q(b.z), q7 = Q(b.w);
    #undef Q

    float4 pk;   // byte values as floats: even -> low nibble, odd -> high
    pk.x = fmaf(q1, 16.0f, q0 + 136.0f);
    pk.y = fmaf(q3, 16.0f, q2 + 136.0f);
    pk.z = fmaf(q5, 16.0f, q4 + 136.0f);
    pk.w = fmaf(q7, 16.0f, q6 + 136.0f);
    out_packed[t] = pk;

    // one scale value per group, written by subgroup lane 0
    if ((threadIdx.x & 3u) == 0u) {
        float ls = fminf(fmaxf(log2f(gmax), -127.0f), 127.0f);
        out_scale[t >> 2] = rintf(ls + 127.0f);
    }
}

extern "C" void kernel_launch(void* const* d_in, const int* in_sizes, int n_in,
                              void* d_out, int out_size)
{
    const float* x = (const float*)d_in[0];
    const long long N = (long long)in_sizes[0];   // 67108864

    float* out = (float*)d_out;                   // [N/2 packed | N/32 scales]
    const long long threads_total = N / 8;        // 8 elements per thread
    const int  block = 256;
    const long long grid = threads_total / block; // N divisible by 2048

    mx_quant_kernel<<<(unsigned int)grid, block>>>(
        (const float4*)x,
        (float4*)out,
        out + (N / 2));
}